// round 3
// baseline (speedup 1.0000x reference)
#include <cuda_runtime.h>

// WaveletLayer: z = leaky_relu(idwt_db2(cA, w0 * cD)), (cA,cD) = dwt_db2(x, 'db2', symmetric)
// x: (65536, 512) fp32 -> out: (65536, 512) fp32.  Warp-per-row, register-resident,
// zero shared memory, zero barriers; halos via warp shuffles; weight hoisted per lane.

#define D_LEN 512
#define THREADS 256
#define BLOCKS  1024   // 8192 warps -> 8 rows per warp (grid-stride)

__global__ __launch_bounds__(THREADS)
void wavelet_warp_kernel(const float* __restrict__ x,
                         const float* __restrict__ w,   // weight row 0, 257 floats
                         float* __restrict__ out,
                         int B)
{
    // db2 filter banks (pywt), fp32
    const float dl0 = -0.12940952255092145f, dl1 = 0.22414386804185735f,
                dl2 =  0.836516303737469f,   dl3 = 0.48296291314469025f;
    const float dh0 = -0.48296291314469025f, dh1 = 0.836516303737469f,
                dh2 = -0.22414386804185735f, dh3 = -0.12940952255092145f;
    const float rl0 =  0.48296291314469025f, rl1 = 0.836516303737469f,
                rl2 =  0.22414386804185735f, rl3 = -0.12940952255092145f;
    const float rh0 = -0.12940952255092145f, rh1 = -0.22414386804185735f,
                rh2 =  0.836516303737469f,   rh3 = -0.48296291314469025f;

    const int lane   = threadIdx.x & 31;
    const int warpId = (blockIdx.x * (THREADS >> 5)) + (threadIdx.x >> 5);
    const int nwarps = gridDim.x * (THREADS >> 5);

    // Hoist weight slice: lane j needs w[8j .. 8j+8] (9 floats), reused for all rows.
    float w8[9];
    #pragma unroll
    for (int m = 0; m < 9; m++) w8[m] = __ldg(w + 8 * lane + m);

    for (int row = warpId; row < B; row += nwarps) {
        const float* xr = x   + (long long)row * D_LEN + 16 * lane;
        float*       zr = out + (long long)row * D_LEN + 16 * lane;

        // ---- load 16 elements per lane: 4 independent LDG.128 ----
        float4 v0 = reinterpret_cast<const float4*>(xr)[0];
        float4 v1 = reinterpret_cast<const float4*>(xr)[1];
        float4 v2 = reinterpret_cast<const float4*>(xr)[2];
        float4 v3 = reinterpret_cast<const float4*>(xr)[3];

        // Padded window X[0..19] = x[16j-2 .. 16j+17]
        float X[20];
        X[2]=v0.x;  X[3]=v0.y;  X[4]=v0.z;  X[5]=v0.w;
        X[6]=v1.x;  X[7]=v1.y;  X[8]=v1.z;  X[9]=v1.w;
        X[10]=v2.x; X[11]=v2.y; X[12]=v2.z; X[13]=v2.w;
        X[14]=v3.x; X[15]=v3.y; X[16]=v3.z; X[17]=v3.w;

        // Backward halo: x[16j-2], x[16j-1] = lane j-1's last two elements
        X[0] = __shfl_up_sync(0xffffffffu, v3.z, 1);
        X[1] = __shfl_up_sync(0xffffffffu, v3.w, 1);
        if (lane == 0) { X[0] = X[3]; X[1] = X[2]; }   // mirror: x[-2]->x[1], x[-1]->x[0]

        // Forward halo: x[16j+16], x[16j+17] = lane j+1's first two elements
        X[18] = __shfl_down_sync(0xffffffffu, v0.x, 1);
        X[19] = __shfl_down_sync(0xffffffffu, v0.y, 1);

        // ---- DWT: A[m]=cA[8j+m], E[m]=w*cD[8j+m] for m=0..8 ----
        // cA[i] = dl0*x[2i+1] + dl1*x[2i] + dl2*x[2i-1] + dl3*x[2i-2]; 2i = 16j+2m.
        float A[9], E[9];
        #pragma unroll
        for (int m = 0; m < 9; m++) {
            const float p0 = X[2*m], p1 = X[2*m+1], p2 = X[2*m+2], p3 = X[2*m+3];
            A[m] =  dl0 * p3 + dl1 * p2 + dl2 * p1 + dl3 * p0;
            E[m] = (dh0 * p3 + dh1 * p2 + dh2 * p1 + dh3 * p0) * w8[m];
        }
        if (lane == 31) {
            // i = 256 mirror tail: x[512]->x[511], x[513]->x[510]  (x510=X[16], x511=X[17])
            A[8] =  dl0 * X[16] + dl1 * X[17] + dl2 * X[17] + dl3 * X[16];
            E[8] = (dh0 * X[16] + dh1 * X[17] + dh2 * X[17] + dh3 * X[16]) * w8[8];
        }

        // ---- iDWT + leaky_relu: 16 outputs per lane ----
        float z[16];
        #pragma unroll
        for (int m = 0; m < 8; m++) {
            float ze = rl2 * A[m] + rl0 * A[m+1] + rh2 * E[m] + rh0 * E[m+1];
            float zo = rl3 * A[m] + rl1 * A[m+1] + rh3 * E[m] + rh1 * E[m+1];
            z[2*m]   = (ze > 0.0f) ? ze : 0.01f * ze;
            z[2*m+1] = (zo > 0.0f) ? zo : 0.01f * zo;
        }

        reinterpret_cast<float4*>(zr)[0] = make_float4(z[0],  z[1],  z[2],  z[3]);
        reinterpret_cast<float4*>(zr)[1] = make_float4(z[4],  z[5],  z[6],  z[7]);
        reinterpret_cast<float4*>(zr)[2] = make_float4(z[8],  z[9],  z[10], z[11]);
        reinterpret_cast<float4*>(zr)[3] = make_float4(z[12], z[13], z[14], z[15]);
    }
}

extern "C" void kernel_launch(void* const* d_in, const int* in_sizes, int n_in,
                              void* d_out, int out_size)
{
    const float* x = (const float*)d_in[0];
    const float* w = (const float*)d_in[1];   // (2, 257); row 0 used
    float* out = (float*)d_out;

    const int B = in_sizes[0] / D_LEN;        // 65536

    wavelet_warp_kernel<<<BLOCKS, THREADS>>>(x, w, out, B);
}

// round 4
// speedup vs baseline: 1.0042x; 1.0042x over previous
#include <cuda_runtime.h>

// WaveletLayer: z = leaky_relu(idwt_db2(cA, w0 * cD)), (cA,cD) = dwt_db2(x, 'db2', symmetric)
// x: (65536, 512) fp32 -> out: (65536, 512) fp32.  Warp-per-row, register-resident,
// zero shared memory, zero barriers; halos via warp shuffles; weight hoisted per lane.

#define D_LEN 512
#define THREADS 256
#define BLOCKS  1024   // 8192 warps -> 8 rows per warp (grid-stride)

__global__ __launch_bounds__(THREADS)
void wavelet_warp_kernel(const float* __restrict__ x,
                         const float* __restrict__ w,   // weight row 0, 257 floats
                         float* __restrict__ out,
                         int B)
{
    // db2 filter banks (pywt), fp32
    const float dl0 = -0.12940952255092145f, dl1 = 0.22414386804185735f,
                dl2 =  0.836516303737469f,   dl3 = 0.48296291314469025f;
    const float dh0 = -0.48296291314469025f, dh1 = 0.836516303737469f,
                dh2 = -0.22414386804185735f, dh3 = -0.12940952255092145f;
    const float rl0 =  0.48296291314469025f, rl1 = 0.836516303737469f,
                rl2 =  0.22414386804185735f, rl3 = -0.12940952255092145f;
    const float rh0 = -0.12940952255092145f, rh1 = -0.22414386804185735f,
                rh2 =  0.836516303737469f,   rh3 = -0.48296291314469025f;

    const int lane   = threadIdx.x & 31;
    const int warpId = (blockIdx.x * (THREADS >> 5)) + (threadIdx.x >> 5);
    const int nwarps = gridDim.x * (THREADS >> 5);

    // Hoist weight slice: lane j needs w[8j .. 8j+8] (9 floats), reused for all rows.
    float w8[9];
    #pragma unroll
    for (int m = 0; m < 9; m++) w8[m] = __ldg(w + 8 * lane + m);

    for (int row = warpId; row < B; row += nwarps) {
        const float* xr = x   + (long long)row * D_LEN + 16 * lane;
        float*       zr = out + (long long)row * D_LEN + 16 * lane;

        // ---- load 16 elements per lane: 4 independent LDG.128 ----
        float4 v0 = reinterpret_cast<const float4*>(xr)[0];
        float4 v1 = reinterpret_cast<const float4*>(xr)[1];
        float4 v2 = reinterpret_cast<const float4*>(xr)[2];
        float4 v3 = reinterpret_cast<const float4*>(xr)[3];

        // Padded window X[0..19] = x[16j-2 .. 16j+17]
        float X[20];
        X[2]=v0.x;  X[3]=v0.y;  X[4]=v0.z;  X[5]=v0.w;
        X[6]=v1.x;  X[7]=v1.y;  X[8]=v1.z;  X[9]=v1.w;
        X[10]=v2.x; X[11]=v2.y; X[12]=v2.z; X[13]=v2.w;
        X[14]=v3.x; X[15]=v3.y; X[16]=v3.z; X[17]=v3.w;

        // Backward halo: x[16j-2], x[16j-1] = lane j-1's last two elements
        X[0] = __shfl_up_sync(0xffffffffu, v3.z, 1);
        X[1] = __shfl_up_sync(0xffffffffu, v3.w, 1);
        if (lane == 0) { X[0] = X[3]; X[1] = X[2]; }   // mirror: x[-2]->x[1], x[-1]->x[0]

        // Forward halo: x[16j+16], x[16j+17] = lane j+1's first two elements
        X[18] = __shfl_down_sync(0xffffffffu, v0.x, 1);
        X[19] = __shfl_down_sync(0xffffffffu, v0.y, 1);

        // ---- DWT: A[m]=cA[8j+m], E[m]=w*cD[8j+m] for m=0..8 ----
        // cA[i] = dl0*x[2i+1] + dl1*x[2i] + dl2*x[2i-1] + dl3*x[2i-2]; 2i = 16j+2m.
        float A[9], E[9];
        #pragma unroll
        for (int m = 0; m < 9; m++) {
            const float p0 = X[2*m], p1 = X[2*m+1], p2 = X[2*m+2], p3 = X[2*m+3];
            A[m] =  dl0 * p3 + dl1 * p2 + dl2 * p1 + dl3 * p0;
            E[m] = (dh0 * p3 + dh1 * p2 + dh2 * p1 + dh3 * p0) * w8[m];
        }
        if (lane == 31) {
            // i = 256 mirror tail: x[512]->x[511], x[513]->x[510]  (x510=X[16], x511=X[17])
            A[8] =  dl0 * X[16] + dl1 * X[17] + dl2 * X[17] + dl3 * X[16];
            E[8] = (dh0 * X[16] + dh1 * X[17] + dh2 * X[17] + dh3 * X[16]) * w8[8];
        }

        // ---- iDWT + leaky_relu: 16 outputs per lane ----
        float z[16];
        #pragma unroll
        for (int m = 0; m < 8; m++) {
            float ze = rl2 * A[m] + rl0 * A[m+1] + rh2 * E[m] + rh0 * E[m+1];
            float zo = rl3 * A[m] + rl1 * A[m+1] + rh3 * E[m] + rh1 * E[m+1];
            z[2*m]   = (ze > 0.0f) ? ze : 0.01f * ze;
            z[2*m+1] = (zo > 0.0f) ? zo : 0.01f * zo;
        }

        reinterpret_cast<float4*>(zr)[0] = make_float4(z[0],  z[1],  z[2],  z[3]);
        reinterpret_cast<float4*>(zr)[1] = make_float4(z[4],  z[5],  z[6],  z[7]);
        reinterpret_cast<float4*>(zr)[2] = make_float4(z[8],  z[9],  z[10], z[11]);
        reinterpret_cast<float4*>(zr)[3] = make_float4(z[12], z[13], z[14], z[15]);
    }
}

extern "C" void kernel_launch(void* const* d_in, const int* in_sizes, int n_in,
                              void* d_out, int out_size)
{
    const float* x = (const float*)d_in[0];
    const float* w = (const float*)d_in[1];   // (2, 257); row 0 used
    float* out = (float*)d_out;

    const int B = in_sizes[0] / D_LEN;        // 65536

    wavelet_warp_kernel<<<BLOCKS, THREADS>>>(x, w, out, B);
}

// round 5
// speedup vs baseline: 1.0072x; 1.0030x over previous
#include <cuda_runtime.h>

// WaveletLayer: z = leaky_relu(idwt_db2(cA, w0 * cD)), (cA,cD) = dwt_db2(x, 'db2', symmetric)
// x: (65536, 512) fp32 -> out: (65536, 512) fp32.  Warp-per-row, register-resident,
// zero shared memory, zero barriers; halos via warp shuffles; weight hoisted per lane.

#define D_LEN 512
#define THREADS 256
#define BLOCKS  1024   // 8192 warps -> 8 rows per warp (grid-stride)

__global__ __launch_bounds__(THREADS)
void wavelet_warp_kernel(const float* __restrict__ x,
                         const float* __restrict__ w,   // weight row 0, 257 floats
                         float* __restrict__ out,
                         int B)
{
    // db2 filter banks (pywt), fp32
    const float dl0 = -0.12940952255092145f, dl1 = 0.22414386804185735f,
                dl2 =  0.836516303737469f,   dl3 = 0.48296291314469025f;
    const float dh0 = -0.48296291314469025f, dh1 = 0.836516303737469f,
                dh2 = -0.22414386804185735f, dh3 = -0.12940952255092145f;
    const float rl0 =  0.48296291314469025f, rl1 = 0.836516303737469f,
                rl2 =  0.22414386804185735f, rl3 = -0.12940952255092145f;
    const float rh0 = -0.12940952255092145f, rh1 = -0.22414386804185735f,
                rh2 =  0.836516303737469f,   rh3 = -0.48296291314469025f;

    const int lane   = threadIdx.x & 31;
    const int warpId = (blockIdx.x * (THREADS >> 5)) + (threadIdx.x >> 5);
    const int nwarps = gridDim.x * (THREADS >> 5);

    // Hoist weight slice: lane j needs w[8j .. 8j+8] (9 floats), reused for all rows.
    float w8[9];
    #pragma unroll
    for (int m = 0; m < 9; m++) w8[m] = __ldg(w + 8 * lane + m);

    for (int row = warpId; row < B; row += nwarps) {
        const float* xr = x   + (long long)row * D_LEN + 16 * lane;
        float*       zr = out + (long long)row * D_LEN + 16 * lane;

        // ---- load 16 elements per lane: 4 independent LDG.128 ----
        float4 v0 = reinterpret_cast<const float4*>(xr)[0];
        float4 v1 = reinterpret_cast<const float4*>(xr)[1];
        float4 v2 = reinterpret_cast<const float4*>(xr)[2];
        float4 v3 = reinterpret_cast<const float4*>(xr)[3];

        // Padded window X[0..19] = x[16j-2 .. 16j+17]
        float X[20];
        X[2]=v0.x;  X[3]=v0.y;  X[4]=v0.z;  X[5]=v0.w;
        X[6]=v1.x;  X[7]=v1.y;  X[8]=v1.z;  X[9]=v1.w;
        X[10]=v2.x; X[11]=v2.y; X[12]=v2.z; X[13]=v2.w;
        X[14]=v3.x; X[15]=v3.y; X[16]=v3.z; X[17]=v3.w;

        // Backward halo: x[16j-2], x[16j-1] = lane j-1's last two elements
        X[0] = __shfl_up_sync(0xffffffffu, v3.z, 1);
        X[1] = __shfl_up_sync(0xffffffffu, v3.w, 1);
        if (lane == 0) { X[0] = X[3]; X[1] = X[2]; }   // mirror: x[-2]->x[1], x[-1]->x[0]

        // Forward halo: x[16j+16], x[16j+17] = lane j+1's first two elements
        X[18] = __shfl_down_sync(0xffffffffu, v0.x, 1);
        X[19] = __shfl_down_sync(0xffffffffu, v0.y, 1);

        // ---- DWT: A[m]=cA[8j+m], E[m]=w*cD[8j+m] for m=0..8 ----
        // cA[i] = dl0*x[2i+1] + dl1*x[2i] + dl2*x[2i-1] + dl3*x[2i-2]; 2i = 16j+2m.
        float A[9], E[9];
        #pragma unroll
        for (int m = 0; m < 9; m++) {
            const float p0 = X[2*m], p1 = X[2*m+1], p2 = X[2*m+2], p3 = X[2*m+3];
            A[m] =  dl0 * p3 + dl1 * p2 + dl2 * p1 + dl3 * p0;
            E[m] = (dh0 * p3 + dh1 * p2 + dh2 * p1 + dh3 * p0) * w8[m];
        }
        if (lane == 31) {
            // i = 256 mirror tail: x[512]->x[511], x[513]->x[510]  (x510=X[16], x511=X[17])
            A[8] =  dl0 * X[16] + dl1 * X[17] + dl2 * X[17] + dl3 * X[16];
            E[8] = (dh0 * X[16] + dh1 * X[17] + dh2 * X[17] + dh3 * X[16]) * w8[8];
        }

        // ---- iDWT + leaky_relu: 16 outputs per lane ----
        float z[16];
        #pragma unroll
        for (int m = 0; m < 8; m++) {
            float ze = rl2 * A[m] + rl0 * A[m+1] + rh2 * E[m] + rh0 * E[m+1];
            float zo = rl3 * A[m] + rl1 * A[m+1] + rh3 * E[m] + rh1 * E[m+1];
            z[2*m]   = (ze > 0.0f) ? ze : 0.01f * ze;
            z[2*m+1] = (zo > 0.0f) ? zo : 0.01f * zo;
        }

        reinterpret_cast<float4*>(zr)[0] = make_float4(z[0],  z[1],  z[2],  z[3]);
        reinterpret_cast<float4*>(zr)[1] = make_float4(z[4],  z[5],  z[6],  z[7]);
        reinterpret_cast<float4*>(zr)[2] = make_float4(z[8],  z[9],  z[10], z[11]);
        reinterpret_cast<float4*>(zr)[3] = make_float4(z[12], z[13], z[14], z[15]);
    }
}

extern "C" void kernel_launch(void* const* d_in, const int* in_sizes, int n_in,
                              void* d_out, int out_size)
{
    const float* x = (const float*)d_in[0];
    const float* w = (const float*)d_in[1];   // (2, 257); row 0 used
    float* out = (float*)d_out;

    const int B = in_sizes[0] / D_LEN;        // 65536

    wavelet_warp_kernel<<<BLOCKS, THREADS>>>(x, w, out, B);
}

// round 7
// speedup vs baseline: 1.0126x; 1.0054x over previous
#include <cuda_runtime.h>

// WaveletLayer: z = leaky_relu(idwt_db2(cA, w0 * cD)), (cA,cD) = dwt_db2(x, 'db2', symmetric)
// x: (65536, 512) fp32 -> out: (65536, 512) fp32.  Warp-per-row, register-resident,
// zero shared memory, zero barriers; halos via warp shuffles; weight hoisted per lane.

#define D_LEN 512
#define THREADS 256
#define BLOCKS  1024   // 8192 warps -> 8 rows per warp (grid-stride)

__global__ __launch_bounds__(THREADS)
void wavelet_warp_kernel(const float* __restrict__ x,
                         const float* __restrict__ w,   // weight row 0, 257 floats
                         float* __restrict__ out,
                         int B)
{
    // db2 filter banks (pywt), fp32
    const float dl0 = -0.12940952255092145f, dl1 = 0.22414386804185735f,
                dl2 =  0.836516303737469f,   dl3 = 0.48296291314469025f;
    const float dh0 = -0.48296291314469025f, dh1 = 0.836516303737469f,
                dh2 = -0.22414386804185735f, dh3 = -0.12940952255092145f;
    const float rl0 =  0.48296291314469025f, rl1 = 0.836516303737469f,
                rl2 =  0.22414386804185735f, rl3 = -0.12940952255092145f;
    const float rh0 = -0.12940952255092145f, rh1 = -0.22414386804185735f,
                rh2 =  0.836516303737469f,   rh3 = -0.48296291314469025f;

    const int lane   = threadIdx.x & 31;
    const int warpId = (blockIdx.x * (THREADS >> 5)) + (threadIdx.x >> 5);
    const int nwarps = gridDim.x * (THREADS >> 5);

    // Hoist weight slice: lane j needs w[8j .. 8j+8] (9 floats), reused for all rows.
    float w8[9];
    #pragma unroll
    for (int m = 0; m < 9; m++) w8[m] = __ldg(w + 8 * lane + m);

    for (int row = warpId; row < B; row += nwarps) {
        const float* xr = x   + (long long)row * D_LEN + 16 * lane;
        float*       zr = out + (long long)row * D_LEN + 16 * lane;

        // ---- load 16 elements per lane: 4 independent LDG.128 ----
        float4 v0 = reinterpret_cast<const float4*>(xr)[0];
        float4 v1 = reinterpret_cast<const float4*>(xr)[1];
        float4 v2 = reinterpret_cast<const float4*>(xr)[2];
        float4 v3 = reinterpret_cast<const float4*>(xr)[3];

        // Padded window X[0..19] = x[16j-2 .. 16j+17]
        float X[20];
        X[2]=v0.x;  X[3]=v0.y;  X[4]=v0.z;  X[5]=v0.w;
        X[6]=v1.x;  X[7]=v1.y;  X[8]=v1.z;  X[9]=v1.w;
        X[10]=v2.x; X[11]=v2.y; X[12]=v2.z; X[13]=v2.w;
        X[14]=v3.x; X[15]=v3.y; X[16]=v3.z; X[17]=v3.w;

        // Backward halo: x[16j-2], x[16j-1] = lane j-1's last two elements
        X[0] = __shfl_up_sync(0xffffffffu, v3.z, 1);
        X[1] = __shfl_up_sync(0xffffffffu, v3.w, 1);
        if (lane == 0) { X[0] = X[3]; X[1] = X[2]; }   // mirror: x[-2]->x[1], x[-1]->x[0]

        // Forward halo: x[16j+16], x[16j+17] = lane j+1's first two elements
        X[18] = __shfl_down_sync(0xffffffffu, v0.x, 1);
        X[19] = __shfl_down_sync(0xffffffffu, v0.y, 1);

        // ---- DWT: A[m]=cA[8j+m], E[m]=w*cD[8j+m] for m=0..8 ----
        // cA[i] = dl0*x[2i+1] + dl1*x[2i] + dl2*x[2i-1] + dl3*x[2i-2]; 2i = 16j+2m.
        float A[9], E[9];
        #pragma unroll
        for (int m = 0; m < 9; m++) {
            const float p0 = X[2*m], p1 = X[2*m+1], p2 = X[2*m+2], p3 = X[2*m+3];
            A[m] =  dl0 * p3 + dl1 * p2 + dl2 * p1 + dl3 * p0;
            E[m] = (dh0 * p3 + dh1 * p2 + dh2 * p1 + dh3 * p0) * w8[m];
        }
        if (lane == 31) {
            // i = 256 mirror tail: x[512]->x[511], x[513]->x[510]  (x510=X[16], x511=X[17])
            A[8] =  dl0 * X[16] + dl1 * X[17] + dl2 * X[17] + dl3 * X[16];
            E[8] = (dh0 * X[16] + dh1 * X[17] + dh2 * X[17] + dh3 * X[16]) * w8[8];
        }

        // ---- iDWT + leaky_relu: 16 outputs per lane ----
        float z[16];
        #pragma unroll
        for (int m = 0; m < 8; m++) {
            float ze = rl2 * A[m] + rl0 * A[m+1] + rh2 * E[m] + rh0 * E[m+1];
            float zo = rl3 * A[m] + rl1 * A[m+1] + rh3 * E[m] + rh1 * E[m+1];
            z[2*m]   = (ze > 0.0f) ? ze : 0.01f * ze;
            z[2*m+1] = (zo > 0.0f) ? zo : 0.01f * zo;
        }

        reinterpret_cast<float4*>(zr)[0] = make_float4(z[0],  z[1],  z[2],  z[3]);
        reinterpret_cast<float4*>(zr)[1] = make_float4(z[4],  z[5],  z[6],  z[7]);
        reinterpret_cast<float4*>(zr)[2] = make_float4(z[8],  z[9],  z[10], z[11]);
        reinterpret_cast<float4*>(zr)[3] = make_float4(z[12], z[13], z[14], z[15]);
    }
}

extern "C" void kernel_launch(void* const* d_in, const int* in_sizes, int n_in,
                              void* d_out, int out_size)
{
    const float* x = (const float*)d_in[0];
    const float* w = (const float*)d_in[1];   // (2, 257); row 0 used
    float* out = (float*)d_out;

    const int B = in_sizes[0] / D_LEN;        // 65536

    wavelet_warp_kernel<<<BLOCKS, THREADS>>>(x, w, out, B);
}